// round 9
// baseline (speedup 1.0000x reference)
#include <cuda_runtime.h>
#include <cuda_bf16.h>
#include <cstdint>

// GCN: out = spmm(A, relu(spmm(A, x@W1)+b1) @ W2) + b2
// N=50000, E=1.6M, 512 -> 128 -> 64.
// GEMM1: mma.sync tf32 (rn), swizzled smem, LDS.128 fragment loads.
// GEMM2: fp32 FFMA. SpMM: on-device CSR (int2 {col,w}) + warp-per-row.
// edge_index is int32 on device (JAX default config downcasts int64).

#define IN_DIM  512
#define HID_DIM 128
#define OUT_DIM 64
#define N_MAX   50000
#define E_MAX   1600000

__device__ float g_S1[(size_t)N_MAX * HID_DIM];  // x @ W1
__device__ float g_H [(size_t)N_MAX * HID_DIM];  // spmm1 out (+b1)
__device__ float g_S2[(size_t)N_MAX * OUT_DIM];  // relu(H) @ W2

// CSR scratch
__device__ int  g_rowptr[N_MAX + 1];
__device__ int  g_rowaux[N_MAX];      // counts, then scatter cursors
__device__ int2 g_edges [E_MAX];      // {colidx, weight-as-int}

// ---------------------------------------------------------------------------
__device__ __forceinline__ float to_tf32_rn(float f) {
    uint32_t o;
    asm("cvt.rn.tf32.f32 %0, %1;" : "=r"(o) : "f"(f));
    return __uint_as_float(o);
}

// ---------------------------------------------------------------------------
// GEMM1: C[M,128] = A[M,512] @ W[512,128] via mma.sync.m16n8k8 tf32.
// Block tile 128x128, BK=32. 8 warps (4 along M x 2 along N), warp tile 32x64.
//
// Swizzled smem layout (per 32-float row): element k lives in chunk
//   ch = (k&3)*2 + ((k>>2)&1), slot = k>>3, physical chunk = ch ^ (row&7).
// A thread's mma fragment (fixed tig, half) for all kk=0..3 is then ONE
// float4: phys = (tig*2+half)^(row&7). Conflict-free per 8-lane phase.
// ---------------------------------------------------------------------------
__global__ __launch_bounds__(256) void gemm1_mma_tf32(
        const float* __restrict__ A, const float* __restrict__ W,
        float* __restrict__ C, int M) {
    constexpr int BM = 128, BN = 128;
    __shared__ float sA[BM * 32];
    __shared__ float sB[BN * 32];

    const int tid  = threadIdx.x;
    const int wid  = tid >> 5;
    const int lane = tid & 31;
    const int gid  = lane >> 2;      // 0..7
    const int tig  = lane & 3;       // 0..3
    const int warpM = (wid & 3) * 32;
    const int warpN = (wid >> 2) * 64;
    const int rowBase = blockIdx.x * BM;

    float acc[2][8][4];
    #pragma unroll
    for (int a = 0; a < 2; a++)
        #pragma unroll
        for (int b = 0; b < 8; b++)
            #pragma unroll
            for (int c = 0; c < 4; c++) acc[a][b][c] = 0.f;

    for (int k0 = 0; k0 < IN_DIM; k0 += 32) {
        // ---- A tile: 128 rows x 32 k (LDG.128 coalesced, swizzled STS.32) --
        #pragma unroll
        for (int i = 0; i < 4; i++) {
            int f = tid + i * 256;
            int r = f >> 3, q = f & 7;
            int m = rowBase + r;
            float4 v = make_float4(0.f, 0.f, 0.f, 0.f);
            if (m < M) v = *(const float4*)(A + (size_t)m * IN_DIM + k0 + q * 4);
            v.x = to_tf32_rn(v.x); v.y = to_tf32_rn(v.y);
            v.z = to_tf32_rn(v.z); v.w = to_tf32_rn(v.w);
            const int rx = r & 7, qh = q & 1, qk = q >> 1;
            float* base = &sA[r * 32 + qk];
            base[((0 | qh) ^ rx) << 2] = v.x;   // j=0: ch=(0<<1)|qh
            base[((2 | qh) ^ rx) << 2] = v.y;   // j=1
            base[((4 | qh) ^ rx) << 2] = v.z;   // j=2
            base[((6 | qh) ^ rx) << 2] = v.w;   // j=3
        }
        // ---- B tile transposed: sB row n holds W[k0..k0+31][n], swizzled ---
        #pragma unroll
        for (int i = 0; i < 16; i++) {
            int f = tid + i * 256;
            int kl = f >> 7, n = f & (BN - 1);
            float v = to_tf32_rn(W[(size_t)(k0 + kl) * BN + n]);
            int ch = ((kl & 3) << 1) | ((kl >> 2) & 1);
            sB[n * 32 + (((ch ^ (n & 7)) << 2) + (kl >> 3))] = v;
        }
        __syncthreads();

        // ---- fragment loads: LDS.128, one per (row, half) covering kk=0..3
        float4 af[2][2][2];   // [mt][rowhalf][half]
        #pragma unroll
        for (int mt = 0; mt < 2; mt++)
            #pragma unroll
            for (int rh = 0; rh < 2; rh++)
                #pragma unroll
                for (int hf = 0; hf < 2; hf++) {
                    int r0 = warpM + mt * 16 + rh * 8 + gid;
                    int phys = ((tig << 1) | hf) ^ (r0 & 7);
                    af[mt][rh][hf] = *(const float4*)&sA[r0 * 32 + (phys << 2)];
                }

        #pragma unroll
        for (int ng = 0; ng < 2; ng++) {
            float4 bv[4][2];
            #pragma unroll
            for (int nt4 = 0; nt4 < 4; nt4++)
                #pragma unroll
                for (int hf = 0; hf < 2; hf++) {
                    int n = warpN + (ng * 4 + nt4) * 8 + gid;
                    int phys = ((tig << 1) | hf) ^ (n & 7);
                    bv[nt4][hf] = *(const float4*)&sB[n * 32 + (phys << 2)];
                }
            #pragma unroll
            for (int kk = 0; kk < 4; kk++) {
                #pragma unroll
                for (int mt = 0; mt < 2; mt++) {
                    uint32_t a0 = __float_as_uint(((const float*)&af[mt][0][0])[kk]);
                    uint32_t a1 = __float_as_uint(((const float*)&af[mt][1][0])[kk]);
                    uint32_t a2 = __float_as_uint(((const float*)&af[mt][0][1])[kk]);
                    uint32_t a3 = __float_as_uint(((const float*)&af[mt][1][1])[kk]);
                    #pragma unroll
                    for (int nt4 = 0; nt4 < 4; nt4++) {
                        int nt = ng * 4 + nt4;
                        uint32_t b0 = __float_as_uint(((const float*)&bv[nt4][0])[kk]);
                        uint32_t b1 = __float_as_uint(((const float*)&bv[nt4][1])[kk]);
                        asm volatile(
                            "mma.sync.aligned.m16n8k8.row.col.f32.tf32.tf32.f32 "
                            "{%0,%1,%2,%3}, {%4,%5,%6,%7}, {%8,%9}, {%0,%1,%2,%3};"
                            : "+f"(acc[mt][nt][0]), "+f"(acc[mt][nt][1]),
                              "+f"(acc[mt][nt][2]), "+f"(acc[mt][nt][3])
                            : "r"(a0), "r"(a1), "r"(a2), "r"(a3),
                              "r"(b0), "r"(b1));
                    }
                }
            }
        }
        __syncthreads();
    }

    #pragma unroll
    for (int mt = 0; mt < 2; mt++) {
        #pragma unroll
        for (int rr = 0; rr < 2; rr++) {
            int m = rowBase + warpM + mt * 16 + rr * 8 + gid;
            if (m < M) {
                float* cp = C + (size_t)m * BN + warpN;
                #pragma unroll
                for (int nt = 0; nt < 8; nt++) {
                    *(float2*)(cp + nt * 8 + 2 * tig) =
                        make_float2(acc[mt][nt][rr * 2 + 0], acc[mt][nt][rr * 2 + 1]);
                }
            }
        }
    }
}

// ---------------------------------------------------------------------------
// fp32 SGEMM for layer 2 (ReLU fused on A load).
// ---------------------------------------------------------------------------
template<int BM, int BN, int BK, bool RELU>
__global__ void sgemm_kernel(const float* __restrict__ A,
                             const float* __restrict__ B,
                             float* __restrict__ C, int M, int K) {
    constexpr int THREADS = (BM / 8) * (BN / 8);
    __shared__ float Ast[BK][BM];
    __shared__ float Bs[BK][BN];

    const int tid  = threadIdx.x;
    const int tcol = tid % (BN / 8);
    const int trow = tid / (BN / 8);
    const int rowBase = blockIdx.x * BM;

    float acc[8][8];
    #pragma unroll
    for (int i = 0; i < 8; i++)
        #pragma unroll
        for (int j = 0; j < 8; j++) acc[i][j] = 0.f;

    for (int k0 = 0; k0 < K; k0 += BK) {
        constexpr int A4 = BM * BK / 4;
        #pragma unroll
        for (int f = tid; f < A4; f += THREADS) {
            int r  = f / (BK / 4);
            int kq = f % (BK / 4);
            int grow = rowBase + r;
            float4 v = make_float4(0.f, 0.f, 0.f, 0.f);
            if (grow < M)
                v = *(const float4*)(A + (size_t)grow * K + k0 + kq * 4);
            if (RELU) {
                v.x = fmaxf(v.x, 0.f); v.y = fmaxf(v.y, 0.f);
                v.z = fmaxf(v.z, 0.f); v.w = fmaxf(v.w, 0.f);
            }
            Ast[kq * 4 + 0][r] = v.x;
            Ast[kq * 4 + 1][r] = v.y;
            Ast[kq * 4 + 2][r] = v.z;
            Ast[kq * 4 + 3][r] = v.w;
        }
        constexpr int B4 = BK * BN / 4;
        #pragma unroll
        for (int f = tid; f < B4; f += THREADS) {
            int kk = f / (BN / 4);
            int c4 = f % (BN / 4);
            *(float4*)&Bs[kk][c4 * 4] =
                *(const float4*)(B + (size_t)(k0 + kk) * BN + c4 * 4);
        }
        __syncthreads();

        #pragma unroll
        for (int kk = 0; kk < BK; kk++) {
            float4 a0 = *(const float4*)&Ast[kk][trow * 8];
            float4 a1 = *(const float4*)&Ast[kk][trow * 8 + 4];
            float4 b0 = *(const float4*)&Bs[kk][tcol * 8];
            float4 b1 = *(const float4*)&Bs[kk][tcol * 8 + 4];
            float a[8] = {a0.x, a0.y, a0.z, a0.w, a1.x, a1.y, a1.z, a1.w};
            float b[8] = {b0.x, b0.y, b0.z, b0.w, b1.x, b1.y, b1.z, b1.w};
            #pragma unroll
            for (int i = 0; i < 8; i++)
                #pragma unroll
                for (int j = 0; j < 8; j++)
                    acc[i][j] = fmaf(a[i], b[j], acc[i][j]);
        }
        __syncthreads();
    }

    #pragma unroll
    for (int i = 0; i < 8; i++) {
        int grow = rowBase + trow * 8 + i;
        if (grow < M) {
            float* cp = C + (size_t)grow * BN + tcol * 8;
            *(float4*)cp       = make_float4(acc[i][0], acc[i][1], acc[i][2], acc[i][3]);
            *(float4*)(cp + 4) = make_float4(acc[i][4], acc[i][5], acc[i][6], acc[i][7]);
        }
    }
}

// ---------------------------------------------------------------------------
// CSR build
// ---------------------------------------------------------------------------
__global__ void zero_counts_kernel(int* __restrict__ cnt, int n) {
    int i = blockIdx.x * blockDim.x + threadIdx.x;
    if (i < n) cnt[i] = 0;
}

__global__ void hist_kernel(const int* __restrict__ rows, int* __restrict__ cnt, int E) {
    int e = blockIdx.x * blockDim.x + threadIdx.x;
    if (e < E) atomicAdd(&cnt[rows[e]], 1);
}

// Single-block exclusive scan over N counts (chunk-per-thread + block scan).
__global__ __launch_bounds__(1024) void scan_kernel(
        int* __restrict__ cnt_and_cursor,   // in: counts, out: cursors (=offsets)
        int* __restrict__ rowptr, int N, int E) {
    __shared__ int part[1024];
    const int t = threadIdx.x;
    const int chunk = (N + 1023) / 1024;
    const int lo = t * chunk;
    const int hi = min(lo + chunk, N);
    int s = 0;
    for (int i = lo; i < hi; i++) s += cnt_and_cursor[i];
    part[t] = s;
    __syncthreads();
    #pragma unroll
    for (int off = 1; off < 1024; off <<= 1) {
        int v = (t >= off) ? part[t - off] : 0;
        __syncthreads();
        part[t] += v;
        __syncthreads();
    }
    int base = (t == 0) ? 0 : part[t - 1];
    for (int i = lo; i < hi; i++) {
        int c = cnt_and_cursor[i];
        rowptr[i] = base;
        cnt_and_cursor[i] = base;   // scatter cursor
        base += c;
    }
    if (t == 0) rowptr[N] = E;
}

__global__ void scatter_kernel(const int* __restrict__ rows,
                               const int* __restrict__ cols,
                               const float* __restrict__ ew,
                               int* __restrict__ cursor,
                               int2* __restrict__ edges, int E) {
    int e = blockIdx.x * blockDim.x + threadIdx.x;
    if (e >= E) return;
    int r = rows[e];
    int pos = atomicAdd(&cursor[r], 1);
    edges[pos] = make_int2(cols[e], __float_as_int(ew[e]));
}

// ---------------------------------------------------------------------------
// CSR SpMM: warp per row, VEC floats per lane (D = 32*VEC).
// dst[row] = bias + sum_j w[j] * src[col[j]]
// ---------------------------------------------------------------------------
template<int VEC>
__global__ void csr_spmm_kernel(const int* __restrict__ rowptr,
                                const int2* __restrict__ edges,
                                const float* __restrict__ src,
                                const float* __restrict__ bias,
                                float* __restrict__ dst, int N) {
    constexpr int D = VEC * 32;
    const int lane = threadIdx.x & 31;
    const int row  = blockIdx.x * (blockDim.x >> 5) + (threadIdx.x >> 5);
    if (row >= N) return;

    const int s = rowptr[row];
    const int e = rowptr[row + 1];

    float acc[VEC];
    #pragma unroll
    for (int v = 0; v < VEC; v++) acc[v] = bias[lane * VEC + v];

    int j = s;
    for (; j + 2 <= e; j += 2) {
        int2 e0 = edges[j], e1 = edges[j + 1];
        float w0 = __int_as_float(e0.y), w1 = __int_as_float(e1.y);
        const float* p0 = src + (size_t)e0.x * D + lane * VEC;
        const float* p1 = src + (size_t)e1.x * D + lane * VEC;
        if (VEC == 4) {
            float4 v0 = *(const float4*)p0;
            float4 v1 = *(const float4*)p1;
            acc[0] = fmaf(w0, v0.x, fmaf(w1, v1.x, acc[0]));
            acc[1] = fmaf(w0, v0.y, fmaf(w1, v1.y, acc[1]));
            acc[2] = fmaf(w0, v0.z, fmaf(w1, v1.z, acc[2]));
            acc[3] = fmaf(w0, v0.w, fmaf(w1, v1.w, acc[3]));
        } else {
            float2 v0 = *(const float2*)p0;
            float2 v1 = *(const float2*)p1;
            acc[0] = fmaf(w0, v0.x, fmaf(w1, v1.x, acc[0]));
            acc[1] = fmaf(w0, v0.y, fmaf(w1, v1.y, acc[1]));
        }
    }
    if (j < e) {
        int2 e0 = edges[j];
        float w0 = __int_as_float(e0.y);
        const float* p0 = src + (size_t)e0.x * D + lane * VEC;
        if (VEC == 4) {
            float4 v0 = *(const float4*)p0;
            acc[0] = fmaf(w0, v0.x, acc[0]);
            acc[1] = fmaf(w0, v0.y, acc[1]);
            acc[2] = fmaf(w0, v0.z, acc[2]);
            acc[3] = fmaf(w0, v0.w, acc[3]);
        } else {
            float2 v0 = *(const float2*)p0;
            acc[0] = fmaf(w0, v0.x, acc[0]);
            acc[1] = fmaf(w0, v0.y, acc[1]);
        }
    }

    float* dp = dst + (size_t)row * D + lane * VEC;
    if (VEC == 4)
        *(float4*)dp = make_float4(acc[0], acc[1], acc[2], acc[3]);
    else
        *(float2*)dp = make_float2(acc[0], acc[1]);
}

// ---------------------------------------------------------------------------
extern "C" void kernel_launch(void* const* d_in, const int* in_sizes, int n_in,
                              void* d_out, int out_size) {
    const float* x  = (const float*)d_in[0];
    const int*   ei = (const int*)d_in[1];     // [2, E] int32
    const float* ew = (const float*)d_in[2];
    const float* W1 = (const float*)d_in[3];
    const float* b1 = (const float*)d_in[4];
    const float* W2 = (const float*)d_in[5];
    const float* b2 = (const float*)d_in[6];
    float* out = (float*)d_out;

    const int M = in_sizes[0] / IN_DIM;   // 50000
    const int E = in_sizes[2];            // 1600000

    float *S1, *H, *S2;
    int *rowptr, *rowaux;
    int2 *edges;
    cudaGetSymbolAddress((void**)&S1, g_S1);
    cudaGetSymbolAddress((void**)&H,  g_H);
    cudaGetSymbolAddress((void**)&S2, g_S2);
    cudaGetSymbolAddress((void**)&rowptr, g_rowptr);
    cudaGetSymbolAddress((void**)&rowaux, g_rowaux);
    cudaGetSymbolAddress((void**)&edges,  g_edges);

    const int* e_rows = ei;
    const int* e_cols = ei + E;

    // --- CSR build (shared by both spmms) ---
    zero_counts_kernel<<<(M + 255) / 256, 256>>>(rowaux, M);
    hist_kernel<<<(E + 255) / 256, 256>>>(e_rows, rowaux, E);
    scan_kernel<<<1, 1024>>>(rowaux, rowptr, M, E);
    scatter_kernel<<<(E + 255) / 256, 256>>>(e_rows, e_cols, ew, rowaux, edges, E);

    // --- GEMM1: S1 = x @ W1 (tf32 mma, swizzled) ---
    gemm1_mma_tf32<<<(M + 127) / 128, 256>>>(x, W1, S1, M);

    // --- SpMM1: H = A @ S1 + b1 ---
    csr_spmm_kernel<4><<<(M + 7) / 8, 256>>>(rowptr, edges, S1, b1, H, M);

    // --- GEMM2: S2 = relu(H) @ W2 (fp32 FFMA) ---
    sgemm_kernel<128, OUT_DIM, 16, true>
        <<<(M + 127) / 128, (128 / 8) * (OUT_DIM / 8)>>>(H, W2, S2, M, HID_DIM);

    // --- SpMM2: out = A @ S2 + b2 ---
    csr_spmm_kernel<2><<<(M + 7) / 8, 256>>>(rowptr, edges, S2, b2, out, M);
}

// round 10
// speedup vs baseline: 1.1630x; 1.1630x over previous
#include <cuda_runtime.h>
#include <cuda_bf16.h>
#include <cstdint>

// GCN: out = spmm(A, relu(spmm(A, x@W1)+b1) @ W2) + b2
// N=50000, E=1.6M, 512 -> 128 -> 64.
// GEMM1: mma.sync tf32 (rn). GEMM2: fp32 FFMA.
// SpMM: on-device CSR (int2 {col,w}) + warp-per-row.
// CSR build runs on a second stream, overlapped with GEMM1 (graph fork/join).
// edge_index is int32 on device (JAX default config downcasts int64).

#define IN_DIM  512
#define HID_DIM 128
#define OUT_DIM 64
#define N_MAX   50000
#define E_MAX   1600000

__device__ float g_S1[(size_t)N_MAX * HID_DIM];  // x @ W1
__device__ float g_H [(size_t)N_MAX * HID_DIM];  // spmm1 out (+b1)
__device__ float g_S2[(size_t)N_MAX * OUT_DIM];  // relu(H) @ W2

// CSR scratch
__device__ int  g_rowptr[N_MAX + 1];
__device__ int  g_rowaux[N_MAX];      // counts, then scatter cursors
__device__ int2 g_edges [E_MAX];      // {colidx, weight-as-int}

// ---------------------------------------------------------------------------
__device__ __forceinline__ float to_tf32_rn(float f) {
    uint32_t o;
    asm("cvt.rn.tf32.f32 %0, %1;" : "=r"(o) : "f"(f));
    return __uint_as_float(o);
}

// ---------------------------------------------------------------------------
// GEMM1: C[M,128] = A[M,512] @ W[512,128] via mma.sync.m16n8k8 tf32.
// Block tile 128x128, BK=32. 8 warps (4 along M x 2 along N), warp tile 32x64.
// (R8 version — the measured-good one.)
// ---------------------------------------------------------------------------
__global__ __launch_bounds__(256) void gemm1_mma_tf32(
        const float* __restrict__ A, const float* __restrict__ W,
        float* __restrict__ C, int M) {
    constexpr int BM = 128, BN = 128, BK = 32, LDA = 36;
    __shared__ float sA[BM * LDA];   // row-major [m][k], padded
    __shared__ float sB[BN * LDA];   // TRANSPOSED [n][k], padded

    const int tid  = threadIdx.x;
    const int wid  = tid >> 5;
    const int lane = tid & 31;
    const int gid  = lane >> 2;      // 0..7
    const int tig  = lane & 3;       // 0..3
    const int warpM = (wid & 3) * 32;
    const int warpN = (wid >> 2) * 64;
    const int rowBase = blockIdx.x * BM;

    float acc[2][8][4];
    #pragma unroll
    for (int a = 0; a < 2; a++)
        #pragma unroll
        for (int b = 0; b < 8; b++)
            #pragma unroll
            for (int c = 0; c < 4; c++) acc[a][b][c] = 0.f;

    for (int k0 = 0; k0 < IN_DIM; k0 += BK) {
        // A tile: 128 x 32 floats (rn-rounded to tf32)
        #pragma unroll
        for (int i = 0; i < 4; i++) {
            int f = tid + i * 256;
            int r = f >> 3, q = f & 7;
            int m = rowBase + r;
            float4 v = make_float4(0.f, 0.f, 0.f, 0.f);
            if (m < M) v = *(const float4*)(A + (size_t)m * IN_DIM + k0 + q * 4);
            v.x = to_tf32_rn(v.x); v.y = to_tf32_rn(v.y);
            v.z = to_tf32_rn(v.z); v.w = to_tf32_rn(v.w);
            *(float4*)&sA[r * LDA + q * 4] = v;
        }
        // B tile transposed: sB[n][kl] = W[k0+kl][n]
        #pragma unroll
        for (int i = 0; i < 16; i++) {
            int f = tid + i * 256;
            int kl = f >> 7, n = f & (BN - 1);
            sB[n * LDA + kl] = to_tf32_rn(W[(size_t)(k0 + kl) * BN + n]);
        }
        __syncthreads();

        #pragma unroll
        for (int kk = 0; kk < 4; kk++) {
            const int k = kk * 8;
            uint32_t bf[8][2];
            #pragma unroll
            for (int nt = 0; nt < 8; nt++) {
                int n = warpN + nt * 8 + gid;
                bf[nt][0] = __float_as_uint(sB[n * LDA + k + tig]);
                bf[nt][1] = __float_as_uint(sB[n * LDA + k + 4 + tig]);
            }
            #pragma unroll
            for (int mt = 0; mt < 2; mt++) {
                int r0 = warpM + mt * 16 + gid;
                uint32_t a0 = __float_as_uint(sA[r0 * LDA + k + tig]);
                uint32_t a1 = __float_as_uint(sA[(r0 + 8) * LDA + k + tig]);
                uint32_t a2 = __float_as_uint(sA[r0 * LDA + k + 4 + tig]);
                uint32_t a3 = __float_as_uint(sA[(r0 + 8) * LDA + k + 4 + tig]);
                #pragma unroll
                for (int nt = 0; nt < 8; nt++) {
                    asm volatile(
                        "mma.sync.aligned.m16n8k8.row.col.f32.tf32.tf32.f32 "
                        "{%0,%1,%2,%3}, {%4,%5,%6,%7}, {%8,%9}, {%0,%1,%2,%3};"
                        : "+f"(acc[mt][nt][0]), "+f"(acc[mt][nt][1]),
                          "+f"(acc[mt][nt][2]), "+f"(acc[mt][nt][3])
                        : "r"(a0), "r"(a1), "r"(a2), "r"(a3),
                          "r"(bf[nt][0]), "r"(bf[nt][1]));
                }
            }
        }
        __syncthreads();
    }

    #pragma unroll
    for (int mt = 0; mt < 2; mt++) {
        #pragma unroll
        for (int rr = 0; rr < 2; rr++) {
            int m = rowBase + warpM + mt * 16 + rr * 8 + gid;
            if (m < M) {
                float* cp = C + (size_t)m * BN + warpN;
                #pragma unroll
                for (int nt = 0; nt < 8; nt++) {
                    *(float2*)(cp + nt * 8 + 2 * tig) =
                        make_float2(acc[mt][nt][rr * 2 + 0], acc[mt][nt][rr * 2 + 1]);
                }
            }
        }
    }
}

// ---------------------------------------------------------------------------
// fp32 SGEMM for layer 2 (ReLU fused on A load).
// ---------------------------------------------------------------------------
template<int BM, int BN, int BK, bool RELU>
__global__ void sgemm_kernel(const float* __restrict__ A,
                             const float* __restrict__ B,
                             float* __restrict__ C, int M, int K) {
    constexpr int THREADS = (BM / 8) * (BN / 8);
    __shared__ float Ast[BK][BM];
    __shared__ float Bs[BK][BN];

    const int tid  = threadIdx.x;
    const int tcol = tid % (BN / 8);
    const int trow = tid / (BN / 8);
    const int rowBase = blockIdx.x * BM;

    float acc[8][8];
    #pragma unroll
    for (int i = 0; i < 8; i++)
        #pragma unroll
        for (int j = 0; j < 8; j++) acc[i][j] = 0.f;

    for (int k0 = 0; k0 < K; k0 += BK) {
        constexpr int A4 = BM * BK / 4;
        #pragma unroll
        for (int f = tid; f < A4; f += THREADS) {
            int r  = f / (BK / 4);
            int kq = f % (BK / 4);
            int grow = rowBase + r;
            float4 v = make_float4(0.f, 0.f, 0.f, 0.f);
            if (grow < M)
                v = *(const float4*)(A + (size_t)grow * K + k0 + kq * 4);
            if (RELU) {
                v.x = fmaxf(v.x, 0.f); v.y = fmaxf(v.y, 0.f);
                v.z = fmaxf(v.z, 0.f); v.w = fmaxf(v.w, 0.f);
            }
            Ast[kq * 4 + 0][r] = v.x;
            Ast[kq * 4 + 1][r] = v.y;
            Ast[kq * 4 + 2][r] = v.z;
            Ast[kq * 4 + 3][r] = v.w;
        }
        constexpr int B4 = BK * BN / 4;
        #pragma unroll
        for (int f = tid; f < B4; f += THREADS) {
            int kk = f / (BN / 4);
            int c4 = f % (BN / 4);
            *(float4*)&Bs[kk][c4 * 4] =
                *(const float4*)(B + (size_t)(k0 + kk) * BN + c4 * 4);
        }
        __syncthreads();

        #pragma unroll
        for (int kk = 0; kk < BK; kk++) {
            float4 a0 = *(const float4*)&Ast[kk][trow * 8];
            float4 a1 = *(const float4*)&Ast[kk][trow * 8 + 4];
            float4 b0 = *(const float4*)&Bs[kk][tcol * 8];
            float4 b1 = *(const float4*)&Bs[kk][tcol * 8 + 4];
            float a[8] = {a0.x, a0.y, a0.z, a0.w, a1.x, a1.y, a1.z, a1.w};
            float b[8] = {b0.x, b0.y, b0.z, b0.w, b1.x, b1.y, b1.z, b1.w};
            #pragma unroll
            for (int i = 0; i < 8; i++)
                #pragma unroll
                for (int j = 0; j < 8; j++)
                    acc[i][j] = fmaf(a[i], b[j], acc[i][j]);
        }
        __syncthreads();
    }

    #pragma unroll
    for (int i = 0; i < 8; i++) {
        int grow = rowBase + trow * 8 + i;
        if (grow < M) {
            float* cp = C + (size_t)grow * BN + tcol * 8;
            *(float4*)cp       = make_float4(acc[i][0], acc[i][1], acc[i][2], acc[i][3]);
            *(float4*)(cp + 4) = make_float4(acc[i][4], acc[i][5], acc[i][6], acc[i][7]);
        }
    }
}

// ---------------------------------------------------------------------------
// CSR build
// ---------------------------------------------------------------------------
__global__ void zero_counts_kernel(int* __restrict__ cnt, int n) {
    int i = blockIdx.x * blockDim.x + threadIdx.x;
    if (i < n) cnt[i] = 0;
}

__global__ void hist_kernel(const int* __restrict__ rows, int* __restrict__ cnt, int E) {
    int e = blockIdx.x * blockDim.x + threadIdx.x;
    if (e < E) atomicAdd(&cnt[rows[e]], 1);
}

// Single-block exclusive scan over N counts (chunk-per-thread + block scan).
__global__ __launch_bounds__(1024) void scan_kernel(
        int* __restrict__ cnt_and_cursor,   // in: counts, out: cursors (=offsets)
        int* __restrict__ rowptr, int N, int E) {
    __shared__ int part[1024];
    const int t = threadIdx.x;
    const int chunk = (N + 1023) / 1024;
    const int lo = t * chunk;
    const int hi = min(lo + chunk, N);
    int s = 0;
    for (int i = lo; i < hi; i++) s += cnt_and_cursor[i];
    part[t] = s;
    __syncthreads();
    #pragma unroll
    for (int off = 1; off < 1024; off <<= 1) {
        int v = (t >= off) ? part[t - off] : 0;
        __syncthreads();
        part[t] += v;
        __syncthreads();
    }
    int base = (t == 0) ? 0 : part[t - 1];
    for (int i = lo; i < hi; i++) {
        int c = cnt_and_cursor[i];
        rowptr[i] = base;
        cnt_and_cursor[i] = base;   // scatter cursor
        base += c;
    }
    if (t == 0) rowptr[N] = E;
}

__global__ void scatter_kernel(const int* __restrict__ rows,
                               const int* __restrict__ cols,
                               const float* __restrict__ ew,
                               int* __restrict__ cursor,
                               int2* __restrict__ edges, int E) {
    int e = blockIdx.x * blockDim.x + threadIdx.x;
    if (e >= E) return;
    int r = rows[e];
    int pos = atomicAdd(&cursor[r], 1);
    edges[pos] = make_int2(cols[e], __float_as_int(ew[e]));
}

// ---------------------------------------------------------------------------
// CSR SpMM: warp per row, VEC floats per lane (D = 32*VEC).
// dst[row] = bias + sum_j w[j] * src[col[j]]
// ---------------------------------------------------------------------------
template<int VEC>
__global__ void csr_spmm_kernel(const int* __restrict__ rowptr,
                                const int2* __restrict__ edges,
                                const float* __restrict__ src,
                                const float* __restrict__ bias,
                                float* __restrict__ dst, int N) {
    constexpr int D = VEC * 32;
    const int lane = threadIdx.x & 31;
    const int row  = blockIdx.x * (blockDim.x >> 5) + (threadIdx.x >> 5);
    if (row >= N) return;

    const int s = rowptr[row];
    const int e = rowptr[row + 1];

    float acc[VEC];
    #pragma unroll
    for (int v = 0; v < VEC; v++) acc[v] = bias[lane * VEC + v];

    int j = s;
    for (; j + 2 <= e; j += 2) {
        int2 e0 = edges[j], e1 = edges[j + 1];
        float w0 = __int_as_float(e0.y), w1 = __int_as_float(e1.y);
        const float* p0 = src + (size_t)e0.x * D + lane * VEC;
        const float* p1 = src + (size_t)e1.x * D + lane * VEC;
        if (VEC == 4) {
            float4 v0 = *(const float4*)p0;
            float4 v1 = *(const float4*)p1;
            acc[0] = fmaf(w0, v0.x, fmaf(w1, v1.x, acc[0]));
            acc[1] = fmaf(w0, v0.y, fmaf(w1, v1.y, acc[1]));
            acc[2] = fmaf(w0, v0.z, fmaf(w1, v1.z, acc[2]));
            acc[3] = fmaf(w0, v0.w, fmaf(w1, v1.w, acc[3]));
        } else {
            float2 v0 = *(const float2*)p0;
            float2 v1 = *(const float2*)p1;
            acc[0] = fmaf(w0, v0.x, fmaf(w1, v1.x, acc[0]));
            acc[1] = fmaf(w0, v0.y, fmaf(w1, v1.y, acc[1]));
        }
    }
    if (j < e) {
        int2 e0 = edges[j];
        float w0 = __int_as_float(e0.y);
        const float* p0 = src + (size_t)e0.x * D + lane * VEC;
        if (VEC == 4) {
            float4 v0 = *(const float4*)p0;
            acc[0] = fmaf(w0, v0.x, acc[0]);
            acc[1] = fmaf(w0, v0.y, acc[1]);
            acc[2] = fmaf(w0, v0.z, acc[2]);
            acc[3] = fmaf(w0, v0.w, acc[3]);
        } else {
            float2 v0 = *(const float2*)p0;
            acc[0] = fmaf(w0, v0.x, acc[0]);
            acc[1] = fmaf(w0, v0.y, acc[1]);
        }
    }

    float* dp = dst + (size_t)row * D + lane * VEC;
    if (VEC == 4)
        *(float4*)dp = make_float4(acc[0], acc[1], acc[2], acc[3]);
    else
        *(float2*)dp = make_float2(acc[0], acc[1]);
}

// ---------------------------------------------------------------------------
extern "C" void kernel_launch(void* const* d_in, const int* in_sizes, int n_in,
                              void* d_out, int out_size) {
    const float* x  = (const float*)d_in[0];
    const int*   ei = (const int*)d_in[1];     // [2, E] int32
    const float* ew = (const float*)d_in[2];
    const float* W1 = (const float*)d_in[3];
    const float* b1 = (const float*)d_in[4];
    const float* W2 = (const float*)d_in[5];
    const float* b2 = (const float*)d_in[6];
    float* out = (float*)d_out;

    const int M = in_sizes[0] / IN_DIM;   // 50000
    const int E = in_sizes[2];            // 1600000

    float *S1, *H, *S2;
    int *rowptr, *rowaux;
    int2 *edges;
    cudaGetSymbolAddress((void**)&S1, g_S1);
    cudaGetSymbolAddress((void**)&H,  g_H);
    cudaGetSymbolAddress((void**)&S2, g_S2);
    cudaGetSymbolAddress((void**)&rowptr, g_rowptr);
    cudaGetSymbolAddress((void**)&rowaux, g_rowaux);
    cudaGetSymbolAddress((void**)&edges,  g_edges);

    const int* e_rows = ei;
    const int* e_cols = ei + E;

    // Side stream + events for fork/join inside graph capture (created once;
    // creation is not device-memory allocation).
    static cudaStream_t s_build = nullptr;
    static cudaEvent_t  ev_fork = nullptr, ev_join = nullptr;
    if (s_build == nullptr) {
        cudaStreamCreateWithFlags(&s_build, cudaStreamNonBlocking);
        cudaEventCreateWithFlags(&ev_fork, cudaEventDisableTiming);
        cudaEventCreateWithFlags(&ev_join, cudaEventDisableTiming);
    }

    // ---- fork: CSR build on s_build, GEMM1 on main stream ----
    cudaEventRecord(ev_fork, 0);
    cudaStreamWaitEvent(s_build, ev_fork, 0);

    zero_counts_kernel<<<(M + 255) / 256, 256, 0, s_build>>>(rowaux, M);
    hist_kernel<<<(E + 255) / 256, 256, 0, s_build>>>(e_rows, rowaux, E);
    scan_kernel<<<1, 1024, 0, s_build>>>(rowaux, rowptr, M, E);
    scatter_kernel<<<(E + 255) / 256, 256, 0, s_build>>>(e_rows, e_cols, ew,
                                                         rowaux, edges, E);
    cudaEventRecord(ev_join, s_build);

    // GEMM1: S1 = x @ W1 (tf32 mma) — concurrent with CSR build
    gemm1_mma_tf32<<<(M + 127) / 128, 256>>>(x, W1, S1, M);

    // ---- join ----
    cudaStreamWaitEvent(0, ev_join, 0);

    // SpMM1: H = A @ S1 + b1
    csr_spmm_kernel<4><<<(M + 7) / 8, 256>>>(rowptr, edges, S1, b1, H, M);

    // GEMM2: S2 = relu(H) @ W2 (fp32 FFMA)
    sgemm_kernel<128, OUT_DIM, 16, true>
        <<<(M + 127) / 128, (128 / 8) * (OUT_DIM / 8)>>>(H, W2, S2, M, HID_DIM);

    // SpMM2: out = A @ S2 + b2
    csr_spmm_kernel<2><<<(M + 7) / 8, 256>>>(rowptr, edges, S2, b2, out, M);
}

// round 11
// speedup vs baseline: 1.2582x; 1.0819x over previous
#include <cuda_runtime.h>
#include <cuda_fp16.h>
#include <cstdint>

// GCN: out = spmm(A, relu(spmm(A, x@W1)+b1) @ W2) + b2
// N=50000, E=1.6M, 512 -> 128 -> 64.
// GEMM1: mma.sync tf32 (rn) -> S1 in fp16. GEMM2: fp32 FFMA -> S2 in fp16.
// SpMM: on-device CSR (int2 {col,w}) + warp-per-row, fp16 gather payload.
// CSR build overlapped with GEMM1 on a second stream (graph fork/join).
// edge_index is int32 on device (JAX default config downcasts int64).

#define IN_DIM  512
#define HID_DIM 128
#define OUT_DIM 64
#define N_MAX   50000
#define E_MAX   1600000

__device__ __half g_S1[(size_t)N_MAX * HID_DIM];  // x @ W1        (fp16)
__device__ float  g_H [(size_t)N_MAX * HID_DIM];  // spmm1 out +b1 (fp32)
__device__ __half g_S2[(size_t)N_MAX * OUT_DIM];  // relu(H) @ W2  (fp16)

// CSR scratch
__device__ int  g_rowptr[N_MAX + 1];
__device__ int  g_rowaux[N_MAX];      // counts, then scatter cursors
__device__ int2 g_edges [E_MAX];      // {colidx, weight-as-int}

// ---------------------------------------------------------------------------
__device__ __forceinline__ float to_tf32_rn(float f) {
    uint32_t o;
    asm("cvt.rn.tf32.f32 %0, %1;" : "=r"(o) : "f"(f));
    return __uint_as_float(o);
}

// ---------------------------------------------------------------------------
// GEMM1: S1[M,128] = A[M,512] @ W[512,128] via mma.sync.m16n8k8 tf32.
// Block tile 128x128, BK=32. 8 warps (4 along M x 2 along N), warp tile 32x64.
// Epilogue stores fp16 (half2).
// ---------------------------------------------------------------------------
__global__ __launch_bounds__(256) void gemm1_mma_tf32(
        const float* __restrict__ A, const float* __restrict__ W,
        __half* __restrict__ C, int M) {
    constexpr int BM = 128, BN = 128, BK = 32, LDA = 36;
    __shared__ float sA[BM * LDA];   // row-major [m][k], padded
    __shared__ float sB[BN * LDA];   // TRANSPOSED [n][k], padded

    const int tid  = threadIdx.x;
    const int wid  = tid >> 5;
    const int lane = tid & 31;
    const int gid  = lane >> 2;      // 0..7
    const int tig  = lane & 3;       // 0..3
    const int warpM = (wid & 3) * 32;
    const int warpN = (wid >> 2) * 64;
    const int rowBase = blockIdx.x * BM;

    float acc[2][8][4];
    #pragma unroll
    for (int a = 0; a < 2; a++)
        #pragma unroll
        for (int b = 0; b < 8; b++)
            #pragma unroll
            for (int c = 0; c < 4; c++) acc[a][b][c] = 0.f;

    for (int k0 = 0; k0 < IN_DIM; k0 += BK) {
        #pragma unroll
        for (int i = 0; i < 4; i++) {
            int f = tid + i * 256;
            int r = f >> 3, q = f & 7;
            int m = rowBase + r;
            float4 v = make_float4(0.f, 0.f, 0.f, 0.f);
            if (m < M) v = *(const float4*)(A + (size_t)m * IN_DIM + k0 + q * 4);
            v.x = to_tf32_rn(v.x); v.y = to_tf32_rn(v.y);
            v.z = to_tf32_rn(v.z); v.w = to_tf32_rn(v.w);
            *(float4*)&sA[r * LDA + q * 4] = v;
        }
        #pragma unroll
        for (int i = 0; i < 16; i++) {
            int f = tid + i * 256;
            int kl = f >> 7, n = f & (BN - 1);
            sB[n * LDA + kl] = to_tf32_rn(W[(size_t)(k0 + kl) * BN + n]);
        }
        __syncthreads();

        #pragma unroll
        for (int kk = 0; kk < 4; kk++) {
            const int k = kk * 8;
            uint32_t bf[8][2];
            #pragma unroll
            for (int nt = 0; nt < 8; nt++) {
                int n = warpN + nt * 8 + gid;
                bf[nt][0] = __float_as_uint(sB[n * LDA + k + tig]);
                bf[nt][1] = __float_as_uint(sB[n * LDA + k + 4 + tig]);
            }
            #pragma unroll
            for (int mt = 0; mt < 2; mt++) {
                int r0 = warpM + mt * 16 + gid;
                uint32_t a0 = __float_as_uint(sA[r0 * LDA + k + tig]);
                uint32_t a1 = __float_as_uint(sA[(r0 + 8) * LDA + k + tig]);
                uint32_t a2 = __float_as_uint(sA[r0 * LDA + k + 4 + tig]);
                uint32_t a3 = __float_as_uint(sA[(r0 + 8) * LDA + k + 4 + tig]);
                #pragma unroll
                for (int nt = 0; nt < 8; nt++) {
                    asm volatile(
                        "mma.sync.aligned.m16n8k8.row.col.f32.tf32.tf32.f32 "
                        "{%0,%1,%2,%3}, {%4,%5,%6,%7}, {%8,%9}, {%0,%1,%2,%3};"
                        : "+f"(acc[mt][nt][0]), "+f"(acc[mt][nt][1]),
                          "+f"(acc[mt][nt][2]), "+f"(acc[mt][nt][3])
                        : "r"(a0), "r"(a1), "r"(a2), "r"(a3),
                          "r"(bf[nt][0]), "r"(bf[nt][1]));
                }
            }
        }
        __syncthreads();
    }

    #pragma unroll
    for (int mt = 0; mt < 2; mt++) {
        #pragma unroll
        for (int rr = 0; rr < 2; rr++) {
            int m = rowBase + warpM + mt * 16 + rr * 8 + gid;
            if (m < M) {
                __half* cp = C + (size_t)m * BN + warpN;
                #pragma unroll
                for (int nt = 0; nt < 8; nt++) {
                    *(__half2*)(cp + nt * 8 + 2 * tig) =
                        __floats2half2_rn(acc[mt][nt][rr * 2 + 0],
                                          acc[mt][nt][rr * 2 + 1]);
                }
            }
        }
    }
}

// ---------------------------------------------------------------------------
// fp32 SGEMM for layer 2 (ReLU fused on A load), fp16 output.
// ---------------------------------------------------------------------------
template<int BM, int BN, int BK, bool RELU>
__global__ void sgemm_kernel(const float* __restrict__ A,
                             const float* __restrict__ B,
                             __half* __restrict__ C, int M, int K) {
    constexpr int THREADS = (BM / 8) * (BN / 8);
    __shared__ float Ast[BK][BM];
    __shared__ float Bs[BK][BN];

    const int tid  = threadIdx.x;
    const int tcol = tid % (BN / 8);
    const int trow = tid / (BN / 8);
    const int rowBase = blockIdx.x * BM;

    float acc[8][8];
    #pragma unroll
    for (int i = 0; i < 8; i++)
        #pragma unroll
        for (int j = 0; j < 8; j++) acc[i][j] = 0.f;

    for (int k0 = 0; k0 < K; k0 += BK) {
        constexpr int A4 = BM * BK / 4;
        #pragma unroll
        for (int f = tid; f < A4; f += THREADS) {
            int r  = f / (BK / 4);
            int kq = f % (BK / 4);
            int grow = rowBase + r;
            float4 v = make_float4(0.f, 0.f, 0.f, 0.f);
            if (grow < M)
                v = *(const float4*)(A + (size_t)grow * K + k0 + kq * 4);
            if (RELU) {
                v.x = fmaxf(v.x, 0.f); v.y = fmaxf(v.y, 0.f);
                v.z = fmaxf(v.z, 0.f); v.w = fmaxf(v.w, 0.f);
            }
            Ast[kq * 4 + 0][r] = v.x;
            Ast[kq * 4 + 1][r] = v.y;
            Ast[kq * 4 + 2][r] = v.z;
            Ast[kq * 4 + 3][r] = v.w;
        }
        constexpr int B4 = BK * BN / 4;
        #pragma unroll
        for (int f = tid; f < B4; f += THREADS) {
            int kk = f / (BN / 4);
            int c4 = f % (BN / 4);
            *(float4*)&Bs[kk][c4 * 4] =
                *(const float4*)(B + (size_t)(k0 + kk) * BN + c4 * 4);
        }
        __syncthreads();

        #pragma unroll
        for (int kk = 0; kk < BK; kk++) {
            float4 a0 = *(const float4*)&Ast[kk][trow * 8];
            float4 a1 = *(const float4*)&Ast[kk][trow * 8 + 4];
            float4 b0 = *(const float4*)&Bs[kk][tcol * 8];
            float4 b1 = *(const float4*)&Bs[kk][tcol * 8 + 4];
            float a[8] = {a0.x, a0.y, a0.z, a0.w, a1.x, a1.y, a1.z, a1.w};
            float b[8] = {b0.x, b0.y, b0.z, b0.w, b1.x, b1.y, b1.z, b1.w};
            #pragma unroll
            for (int i = 0; i < 8; i++)
                #pragma unroll
                for (int j = 0; j < 8; j++)
                    acc[i][j] = fmaf(a[i], b[j], acc[i][j]);
        }
        __syncthreads();
    }

    #pragma unroll
    for (int i = 0; i < 8; i++) {
        int grow = rowBase + trow * 8 + i;
        if (grow < M) {
            __half* cp = C + (size_t)grow * BN + tcol * 8;
            __half2 h0 = __floats2half2_rn(acc[i][0], acc[i][1]);
            __half2 h1 = __floats2half2_rn(acc[i][2], acc[i][3]);
            __half2 h2 = __floats2half2_rn(acc[i][4], acc[i][5]);
            __half2 h3 = __floats2half2_rn(acc[i][6], acc[i][7]);
            uint4 u;
            u.x = *(uint32_t*)&h0; u.y = *(uint32_t*)&h1;
            u.z = *(uint32_t*)&h2; u.w = *(uint32_t*)&h3;
            *(uint4*)cp = u;
        }
    }
}

// ---------------------------------------------------------------------------
// CSR build
// ---------------------------------------------------------------------------
__global__ void zero_counts_kernel(int* __restrict__ cnt, int n) {
    int i = blockIdx.x * blockDim.x + threadIdx.x;
    if (i < n) cnt[i] = 0;
}

__global__ void hist_kernel(const int* __restrict__ rows, int* __restrict__ cnt, int E) {
    int e = blockIdx.x * blockDim.x + threadIdx.x;
    if (e < E) atomicAdd(&cnt[rows[e]], 1);
}

__global__ __launch_bounds__(1024) void scan_kernel(
        int* __restrict__ cnt_and_cursor, int* __restrict__ rowptr, int N, int E) {
    __shared__ int part[1024];
    const int t = threadIdx.x;
    const int chunk = (N + 1023) / 1024;
    const int lo = t * chunk;
    const int hi = min(lo + chunk, N);
    int s = 0;
    for (int i = lo; i < hi; i++) s += cnt_and_cursor[i];
    part[t] = s;
    __syncthreads();
    #pragma unroll
    for (int off = 1; off < 1024; off <<= 1) {
        int v = (t >= off) ? part[t - off] : 0;
        __syncthreads();
        part[t] += v;
        __syncthreads();
    }
    int base = (t == 0) ? 0 : part[t - 1];
    for (int i = lo; i < hi; i++) {
        int c = cnt_and_cursor[i];
        rowptr[i] = base;
        cnt_and_cursor[i] = base;
        base += c;
    }
    if (t == 0) rowptr[N] = E;
}

__global__ void scatter_kernel(const int* __restrict__ rows,
                               const int* __restrict__ cols,
                               const float* __restrict__ ew,
                               int* __restrict__ cursor,
                               int2* __restrict__ edges, int E) {
    int e = blockIdx.x * blockDim.x + threadIdx.x;
    if (e >= E) return;
    int r = rows[e];
    int pos = atomicAdd(&cursor[r], 1);
    edges[pos] = make_int2(cols[e], __float_as_int(ew[e]));
}

// ---------------------------------------------------------------------------
// CSR SpMM with fp16 payload: warp per row, VEC fp16 values per lane
// (D = 32*VEC halfs per row). dst[row] = bias + sum_j w[j] * src[col[j]]
// ---------------------------------------------------------------------------
template<int VEC>
__global__ void csr_spmm_h_kernel(const int* __restrict__ rowptr,
                                  const int2* __restrict__ edges,
                                  const __half* __restrict__ src,
                                  const float* __restrict__ bias,
                                  float* __restrict__ dst, int N) {
    constexpr int D = VEC * 32;
    const int lane = threadIdx.x & 31;
    const int row  = blockIdx.x * (blockDim.x >> 5) + (threadIdx.x >> 5);
    if (row >= N) return;

    const int s = rowptr[row];
    const int e = rowptr[row + 1];

    float acc[VEC];
    #pragma unroll
    for (int v = 0; v < VEC; v++) acc[v] = bias[lane * VEC + v];

    int j = s;
    for (; j + 2 <= e; j += 2) {
        int2 e0 = edges[j], e1 = edges[j + 1];
        float w0 = __int_as_float(e0.y), w1 = __int_as_float(e1.y);
        const __half* p0 = src + (size_t)e0.x * D + lane * VEC;
        const __half* p1 = src + (size_t)e1.x * D + lane * VEC;
        if (VEC == 4) {
            uint2 u0 = *(const uint2*)p0;
            uint2 u1 = *(const uint2*)p1;
            float2 a0 = __half22float2(*(const __half2*)&u0.x);
            float2 a1 = __half22float2(*(const __half2*)&u0.y);
            float2 c0 = __half22float2(*(const __half2*)&u1.x);
            float2 c1 = __half22float2(*(const __half2*)&u1.y);
            acc[0] = fmaf(w0, a0.x, fmaf(w1, c0.x, acc[0]));
            acc[1] = fmaf(w0, a0.y, fmaf(w1, c0.y, acc[1]));
            acc[2] = fmaf(w0, a1.x, fmaf(w1, c1.x, acc[2]));
            acc[3] = fmaf(w0, a1.y, fmaf(w1, c1.y, acc[3]));
        } else {
            float2 a0 = __half22float2(*(const __half2*)p0);
            float2 c0 = __half22float2(*(const __half2*)p1);
            acc[0] = fmaf(w0, a0.x, fmaf(w1, c0.x, acc[0]));
            acc[1] = fmaf(w0, a0.y, fmaf(w1, c0.y, acc[1]));
        }
    }
    if (j < e) {
        int2 e0 = edges[j];
        float w0 = __int_as_float(e0.y);
        const __half* p0 = src + (size_t)e0.x * D + lane * VEC;
        if (VEC == 4) {
            uint2 u0 = *(const uint2*)p0;
            float2 a0 = __half22float2(*(const __half2*)&u0.x);
            float2 a1 = __half22float2(*(const __half2*)&u0.y);
            acc[0] = fmaf(w0, a0.x, acc[0]);
            acc[1] = fmaf(w0, a0.y, acc[1]);
            acc[2] = fmaf(w0, a1.x, acc[2]);
            acc[3] = fmaf(w0, a1.y, acc[3]);
        } else {
            float2 a0 = __half22float2(*(const __half2*)p0);
            acc[0] = fmaf(w0, a0.x, acc[0]);
            acc[1] = fmaf(w0, a0.y, acc[1]);
        }
    }

    float* dp = dst + (size_t)row * D + lane * VEC;
    if (VEC == 4)
        *(float4*)dp = make_float4(acc[0], acc[1], acc[2], acc[3]);
    else
        *(float2*)dp = make_float2(acc[0], acc[1]);
}

// ---------------------------------------------------------------------------
extern "C" void kernel_launch(void* const* d_in, const int* in_sizes, int n_in,
                              void* d_out, int out_size) {
    const float* x  = (const float*)d_in[0];
    const int*   ei = (const int*)d_in[1];     // [2, E] int32
    const float* ew = (const float*)d_in[2];
    const float* W1 = (const float*)d_in[3];
    const float* b1 = (const float*)d_in[4];
    const float* W2 = (const float*)d_in[5];
    const float* b2 = (const float*)d_in[6];
    float* out = (float*)d_out;

    const int M = in_sizes[0] / IN_DIM;   // 50000
    const int E = in_sizes[2];            // 1600000

    __half *S1, *S2;
    float *H;
    int *rowptr, *rowaux;
    int2 *edges;
    cudaGetSymbolAddress((void**)&S1, g_S1);
    cudaGetSymbolAddress((void**)&H,  g_H);
    cudaGetSymbolAddress((void**)&S2, g_S2);
    cudaGetSymbolAddress((void**)&rowptr, g_rowptr);
    cudaGetSymbolAddress((void**)&rowaux, g_rowaux);
    cudaGetSymbolAddress((void**)&edges,  g_edges);

    const int* e_rows = ei;
    const int* e_cols = ei + E;

    static cudaStream_t s_build = nullptr;
    static cudaEvent_t  ev_fork = nullptr, ev_join = nullptr;
    if (s_build == nullptr) {
        cudaStreamCreateWithFlags(&s_build, cudaStreamNonBlocking);
        cudaEventCreateWithFlags(&ev_fork, cudaEventDisableTiming);
        cudaEventCreateWithFlags(&ev_join, cudaEventDisableTiming);
    }

    // ---- fork: CSR build on s_build, GEMM1 on main stream ----
    cudaEventRecord(ev_fork, 0);
    cudaStreamWaitEvent(s_build, ev_fork, 0);

    zero_counts_kernel<<<(M + 255) / 256, 256, 0, s_build>>>(rowaux, M);
    hist_kernel<<<(E + 255) / 256, 256, 0, s_build>>>(e_rows, rowaux, E);
    scan_kernel<<<1, 1024, 0, s_build>>>(rowaux, rowptr, M, E);
    scatter_kernel<<<(E + 255) / 256, 256, 0, s_build>>>(e_rows, e_cols, ew,
                                                         rowaux, edges, E);
    cudaEventRecord(ev_join, s_build);

    // GEMM1: S1 = x @ W1 (tf32 mma, fp16 out) — concurrent with CSR build
    gemm1_mma_tf32<<<(M + 127) / 128, 256>>>(x, W1, S1, M);

    // ---- join ----
    cudaStreamWaitEvent(0, ev_join, 0);

    // SpMM1: H = A @ S1 + b1   (fp16 gather, fp32 accumulate)
    csr_spmm_h_kernel<4><<<(M + 7) / 8, 256>>>(rowptr, edges, S1, b1, H, M);

    // GEMM2: S2 = relu(H) @ W2 (fp32 FFMA, fp16 out)
    sgemm_kernel<128, OUT_DIM, 16, true>
        <<<(M + 127) / 128, (128 / 8) * (OUT_DIM / 8)>>>(H, W2, S2, M, HID_DIM);

    // SpMM2: out = A @ S2 + b2  (fp16 gather, fp32 accumulate/output)
    csr_spmm_h_kernel<2><<<(M + 7) / 8, 256>>>(rowptr, edges, S2, b2, out, M);
}